// round 12
// baseline (speedup 1.0000x reference)
#include <cuda_runtime.h>
#include <cuda_bf16.h>
#include <cstdint>

// ============================================================================
// VersorLinear == one 8192x8192x8192 GEMM with a signed/permuted weight:
//   out[bs, o*32+k] = sum_{i,l} x[bs, i*32+l] * sign(k^l, l) * weight[o,i,k^l]
// followed by per-(bs,o) manifold normalization over the 32 components.
//
// R11: cg2 GEMM with exemplar-proven synchronization: per-stage split
// barrier.cluster (arrive -> refill -> wait -> MMA) replaces the custom
// mapa-arrive full-barrier handshake (suspected cause of R10's 5.8e-2 error).
// M=256 x N=256 pair tiles, BK=64, 3-stage cp.async, multicast commit,
// 3-term bf16 split, fp32 TMEM acc, fused normalization.
// ============================================================================

#if defined(__CUDA_ARCH_FEAT_SM103_ALL) || defined(__CUDA_ARCH_FEAT_SM100_ALL) || \
    defined(__CUDA_ARCH_FEAT_SM101_ALL) ||                                        \
    (defined(__CUDA_ARCH_SPECIFIC__) && (__CUDA_ARCH_SPECIFIC__ == 1030 || __CUDA_ARCH_SPECIFIC__ == 1000))
#define HAS_TCGEN05 1
#else
#define HAS_TCGEN05 0
#endif

static constexpr int MDIM = 8192;   // B*S
static constexpr int NDIM = 8192;   // OUT_F*32
static constexpr int KDIM = 8192;   // IN_F*32
static constexpr int IFEA = 256;

// ---- static device scratch (1024-aligned for 16B vector access) ----
__device__ __align__(1024) float g_sign[1024];
__device__ __align__(1024) __nv_bfloat16 g_Xh[(size_t)MDIM * KDIM];
__device__ __align__(1024) __nv_bfloat16 g_Xl[(size_t)MDIM * KDIM];
__device__ __align__(1024) __nv_bfloat16 g_Wh[(size_t)NDIM * KDIM];
__device__ __align__(1024) __nv_bfloat16 g_Wl[(size_t)NDIM * KDIM];

// ============================ common helpers ================================
__device__ __forceinline__ uint32_t smem_u32(const void* p) {
    uint32_t a;
    asm("{ .reg .u64 t; cvta.to.shared.u64 t, %1; cvt.u32.u64 %0, t; }"
        : "=r"(a) : "l"(p));
    return a;
}

__device__ __forceinline__ void cp16(uint32_t sdst, const void* gsrc) {
    asm volatile("cp.async.cg.shared.global [%0], [%1], 16;"
                 :: "r"(sdst), "l"(gsrc));
}

__device__ __forceinline__ bool elect_one() {
    uint32_t p;
    asm volatile(
        "{\n\t.reg .pred p;\n\t"
        "elect.sync _|p, 0xFFFFFFFF;\n\t"
        "selp.b32 %0, 1, 0, p;\n\t}"
        : "=r"(p));
    return p != 0;
}

// metric signature factor for blade k
__device__ __forceinline__ float sig_of(int k) {
    const int g = __popc(k);
    const int neg = ((k >> 4) & 1) ^ ((g * (g - 1) / 2) & 1);
    return neg ? -1.f : 1.f;
}

// ============================ tcgen05 helpers ===============================
#if HAS_TCGEN05

__device__ __forceinline__ uint32_t cluster_rank() {
    uint32_t r;
    asm("mov.u32 %0, %%cluster_ctarank;" : "=r"(r));
    return r;
}

#define TCGEN05_ALLOC_CG2(smem_addr, ncols) \
    asm volatile("tcgen05.alloc.cta_group::2.sync.aligned.shared::cta.b32 [%0], %1;" \
                 :: "r"((uint32_t)(smem_addr)), "r"((uint32_t)(ncols)) : "memory")
#define TCGEN05_RELINQ_CG2() \
    asm volatile("tcgen05.relinquish_alloc_permit.cta_group::2.sync.aligned;")
#define TCGEN05_DEALLOC_CG2(tmem, ncols) \
    asm volatile("tcgen05.dealloc.cta_group::2.sync.aligned.b32 %0, %1;" \
                 :: "r"(tmem), "r"((uint32_t)(ncols)))
#define TCGEN05_COMMIT_MC_CG2(mbar, mask) \
    asm volatile("tcgen05.commit.cta_group::2.mbarrier::arrive::one.shared::cluster.multicast::cluster.b64 [%0], %1;" \
                 :: "r"((uint32_t)(mbar)), "h"((uint16_t)(mask)) : "memory")
#define TCGEN05_WAIT_LD() asm volatile("tcgen05.wait::ld.sync.aligned;" ::: "memory")
#define TCGEN05_FENCE_AFTER() asm volatile("tcgen05.fence::after_thread_sync;" ::: "memory")
#define MBARRIER_INIT(mbar, count) \
    asm volatile("mbarrier.init.shared.b64 [%0], %1;" \
                 :: "r"((uint32_t)(mbar)), "r"((uint32_t)(count)) : "memory")
#define MBARRIER_INVAL(mbar) \
    asm volatile("mbarrier.inval.shared.b64 [%0];" :: "r"((uint32_t)(mbar)) : "memory")

#define MBARRIER_WAIT_PARITY(mbar_addr, phase_parity) do {                          \
    uint32_t _mbar = (uint32_t)(mbar_addr);                                         \
    uint32_t _parity = (uint32_t)(phase_parity);                                    \
    uint32_t _done;                                                                 \
    asm volatile(                                                                   \
        "{\n\t.reg .pred p;\n\t"                                                    \
        "mbarrier.try_wait.parity.acquire.cta.shared::cta.b64 p, [%1], %2;\n\t"     \
        "selp.b32 %0, 1, 0, p;\n\t}"                                                \
        : "=r"(_done) : "r"(_mbar), "r"(_parity) : "memory");                       \
    if (!_done) {                                                                   \
        asm volatile(                                                               \
            "{\n\t.reg .pred P1;\n\t"                                               \
            "WAIT_LOOP_%=:\n\t"                                                     \
            "mbarrier.try_wait.parity.acquire.cta.shared::cta.b64 P1, [%0], %1, 0x989680;\n\t" \
            "@P1 bra.uni WAIT_DONE_%=;\n\t"                                         \
            "bra.uni WAIT_LOOP_%=;\n\t"                                             \
            "WAIT_DONE_%=:\n\t}"                                                    \
            :: "r"(_mbar), "r"(_parity) : "memory");                                \
    }                                                                               \
} while (0)

#define TCGEN05_LD_32X32B_X32(r, tmem_addr) \
    asm volatile( \
        "tcgen05.ld.sync.aligned.32x32b.x32.b32 " \
        "{%0, %1, %2, %3, %4, %5, %6, %7, " \
        " %8, %9, %10, %11, %12, %13, %14, %15, " \
        " %16, %17, %18, %19, %20, %21, %22, %23, " \
        " %24, %25, %26, %27, %28, %29, %30, %31}, [%32];" \
        : "=r"((r)[0]),  "=r"((r)[1]),  "=r"((r)[2]),  "=r"((r)[3]), \
          "=r"((r)[4]),  "=r"((r)[5]),  "=r"((r)[6]),  "=r"((r)[7]), \
          "=r"((r)[8]),  "=r"((r)[9]),  "=r"((r)[10]), "=r"((r)[11]), \
          "=r"((r)[12]), "=r"((r)[13]), "=r"((r)[14]), "=r"((r)[15]), \
          "=r"((r)[16]), "=r"((r)[17]), "=r"((r)[18]), "=r"((r)[19]), \
          "=r"((r)[20]), "=r"((r)[21]), "=r"((r)[22]), "=r"((r)[23]), \
          "=r"((r)[24]), "=r"((r)[25]), "=r"((r)[26]), "=r"((r)[27]), \
          "=r"((r)[28]), "=r"((r)[29]), "=r"((r)[30]), "=r"((r)[31]) \
        : "r"(tmem_addr))

static constexpr uint64_t DESC_BASE_SW128 =
    (uint64_t(2) << 61) | (uint64_t(1) << 46) | (uint64_t(64) << 32) | (uint64_t(1) << 16);

__device__ __forceinline__ uint64_t make_desc(uint32_t addr) {
    return DESC_BASE_SW128 | ((uint64_t)(addr >> 4) & 0x3FFF);
}

// cg2 bf16 SS MMA: disable-output-lane vector is 8 regs for cta_group::2
__device__ __forceinline__ void mma_ss_f16_cg2(uint32_t d, uint64_t a, uint64_t b,
                                               uint32_t idesc, uint32_t en) {
    asm volatile(
        "{\n\t.reg .pred p;\n\t"
        "setp.ne.u32 p, %4, 0;\n\t"
        "tcgen05.mma.cta_group::2.kind::f16 [%0], %1, %2, %3, "
        "{%5, %5, %5, %5, %5, %5, %5, %5}, p;\n\t}"
        :: "r"(d), "l"(a), "l"(b), "r"(idesc), "r"(en), "r"(0u)
        : "memory");
}

#define CLUSTER_ARRIVE() \
    asm volatile("barrier.cluster.arrive.aligned;" ::: "memory")
#define CLUSTER_WAIT() \
    asm volatile("barrier.cluster.wait.aligned;" ::: "memory")
#define CLUSTER_SYNC() do { CLUSTER_ARRIVE(); CLUSTER_WAIT(); } while (0)

#endif // HAS_TCGEN05

// ============================ HMMA helpers (fallback) =======================
#if !HAS_TCGEN05
__device__ __forceinline__ void ldsm_x4(uint32_t* r, uint32_t addr) {
    asm volatile("ldmatrix.sync.aligned.m8n8.x4.shared.b16 {%0,%1,%2,%3}, [%4];"
                 : "=r"(r[0]), "=r"(r[1]), "=r"(r[2]), "=r"(r[3]) : "r"(addr));
}
__device__ __forceinline__ void ldsm_x2(uint32_t* r, uint32_t addr) {
    asm volatile("ldmatrix.sync.aligned.m8n8.x2.shared.b16 {%0,%1}, [%2];"
                 : "=r"(r[0]), "=r"(r[1]) : "r"(addr));
}
__device__ __forceinline__ void mma16816(float* c, const uint32_t* a, const uint32_t* b) {
    asm volatile(
        "mma.sync.aligned.m16n8k16.row.col.f32.bf16.bf16.f32 "
        "{%0,%1,%2,%3}, {%4,%5,%6,%7}, {%8,%9}, {%0,%1,%2,%3};"
        : "+f"(c[0]), "+f"(c[1]), "+f"(c[2]), "+f"(c[3])
        : "r"(a[0]), "r"(a[1]), "r"(a[2]), "r"(a[3]), "r"(b[0]), "r"(b[1]));
}
#endif

// ============================ builder kernels ===============================
__global__ void init_sign_k() {
    int a = threadIdx.x, b = threadIdx.y;
    float s = 1.f;
    int bits = a;
    for (int i = 0; i < 5; i++) {
        if ((b >> i) & 1) {
            for (int j = i + 1; j < 5; j++)
                if ((bits >> j) & 1) s = -s;
            if ((bits >> i) & 1) {
                if (i == 4) s = -s;   // e5^2 = -1
                bits &= ~(1 << i);
            } else {
                bits |= (1 << i);
            }
        }
    }
    g_sign[a * 32 + b] = s;
}

__global__ void __launch_bounds__(256) cvt_x_k(const float* __restrict__ x) {
    const size_t i = ((size_t)blockIdx.x * blockDim.x + threadIdx.x) * 4;
    const float4 v = *(const float4*)(x + i);
    __nv_bfloat16 h0 = __float2bfloat16(v.x);
    __nv_bfloat16 h1 = __float2bfloat16(v.y);
    __nv_bfloat16 h2 = __float2bfloat16(v.z);
    __nv_bfloat16 h3 = __float2bfloat16(v.w);
    __nv_bfloat16 l0 = __float2bfloat16(v.x - __bfloat162float(h0));
    __nv_bfloat16 l1 = __float2bfloat16(v.y - __bfloat162float(h1));
    __nv_bfloat16 l2 = __float2bfloat16(v.z - __bfloat162float(h2));
    __nv_bfloat16 l3 = __float2bfloat16(v.w - __bfloat162float(h3));
    __nv_bfloat162 H01 = __halves2bfloat162(h0, h1);
    __nv_bfloat162 H23 = __halves2bfloat162(h2, h3);
    __nv_bfloat162 L01 = __halves2bfloat162(l0, l1);
    __nv_bfloat162 L23 = __halves2bfloat162(l2, l3);
    uint2 uh, ul;
    uh.x = *(uint32_t*)&H01; uh.y = *(uint32_t*)&H23;
    ul.x = *(uint32_t*)&L01; ul.y = *(uint32_t*)&L23;
    *(uint2*)(g_Xh + i) = uh;
    *(uint2*)(g_Xl + i) = ul;
}

__global__ void __launch_bounds__(256) build_w_k(const float* __restrict__ w) {
    const size_t idx = ((size_t)blockIdx.x * blockDim.x + threadIdx.x) * 4;
    const int q = (int)(idx & 8191);     // (i,l)
    const int n = (int)(idx >> 13);      // (o,k)
    const int l0 = q & 31, i = q >> 5;
    const int k = n & 31, o = n >> 5;
    const float* wrow = w + ((size_t)(o * IFEA + i) << 5);

    __nv_bfloat16 h[4], lo[4];
    #pragma unroll
    for (int d = 0; d < 4; d++) {
        const int l = l0 + d;
        const int j = k ^ l;
        const float v = g_sign[j * 32 + l] * wrow[j];
        h[d] = __float2bfloat16(v);
        lo[d] = __float2bfloat16(v - __bfloat162float(h[d]));
    }
    __nv_bfloat162 H01 = __halves2bfloat162(h[0], h[1]);
    __nv_bfloat162 H23 = __halves2bfloat162(h[2], h[3]);
    __nv_bfloat162 L01 = __halves2bfloat162(lo[0], lo[1]);
    __nv_bfloat162 L23 = __halves2bfloat162(lo[2], lo[3]);
    uint2 uh, ul;
    uh.x = *(uint32_t*)&H01; uh.y = *(uint32_t*)&H23;
    ul.x = *(uint32_t*)&L01; ul.y = *(uint32_t*)&L23;
    *(uint2*)(g_Wh + idx) = uh;
    *(uint2*)(g_Wl + idx) = ul;
}

// ====================== tcgen05 cg2 GEMM (main) =============================
// Pair tile: M=256, N=256, BK=64. Per CTA per stage: Ah/Al (16KB each, its
// 128 M-rows) + Bh/Bl (16KB each, its 128 N-rows = N/2 split). 64KB * 3 stages.
static constexpr int TC_ST      = 65536;
static constexpr int TC_OFF_AH  = 0;
static constexpr int TC_OFF_AL  = 16384;
static constexpr int TC_OFF_BH  = 32768;
static constexpr int TC_OFF_BL  = 49152;
static constexpr int TC_HDR     = 3 * TC_ST;        // 196608
static constexpr int TC_SMEM    = TC_HDR + 32;
// header: +0 tmem ptr, +8 mma[0], +16 mma[1] (multicast commit targets)

// idesc: dtype=F32, a=BF16, b=BF16, N=256, M=256
static constexpr uint32_t TC_IDESC =
    (1u << 4) | (1u << 7) | (1u << 10) | ((256u / 8) << 17) | ((256u / 16) << 24);

__global__ void __launch_bounds__(256) __cluster_dims__(2, 1, 1)
versor_tc(float* __restrict__ out) {
#if HAS_TCGEN05
    extern __shared__ __align__(1024) char smem[];
    const uint32_t sb = smem_u32(smem);
    const int tid  = threadIdx.x;
    const int warp = tid >> 5;
    const int lane = tid & 31;
    const uint32_t rank = cluster_rank();

    // cg2 TMEM alloc: warp 0 of BOTH CTAs participates. No relinquish race.
    if (warp == 0) { TCGEN05_ALLOC_CG2(sb + TC_HDR, 256); }
    if (tid == 0) {
        MBARRIER_INIT(sb + TC_HDR + 8, 1);   // mma[0]
        MBARRIER_INIT(sb + TC_HDR + 16, 1);  // mma[1]
    }
    __syncthreads();
    CLUSTER_SYNC();   // mbars initialized before any multicast commit arrives

    uint32_t tmem;
    asm volatile("ld.shared.b32 %0, [%1];" : "=r"(tmem) : "r"(sb + TC_HDR));

    // pair-tile grid: 32 (M) x 32 (N); grouped raster GM=8 over pairs
    const int pair = blockIdx.x >> 1;
    const int grp  = pair >> 8;          // / (8*32)
    const int rem  = pair & 255;
    const int pm   = (grp << 3) + (rem & 7);
    const int pn   = rem >> 3;
    const int bm   = pm * 256;
    const int bn   = pn * 256;

    // this CTA's slices: A rows [bm + rank*128, +128), B rows [bn + rank*128, +128)
    const char* srcAh = (const char*)(g_Xh + (size_t)(bm + rank * 128) * KDIM);
    const char* srcAl = (const char*)(g_Xl + (size_t)(bm + rank * 128) * KDIM);
    const char* srcBh = (const char*)(g_Wh + (size_t)(bn + rank * 128) * KDIM);
    const char* srcBl = (const char*)(g_Wl + (size_t)(bn + rank * 128) * KDIM);
    const size_t rs = (size_t)KDIM * 2;

    auto fill = [&](int stage, int ktile) {
        const uint32_t st = sb + stage * TC_ST;
        const size_t kb = (size_t)ktile * 128;   // 64 k * 2B
        #pragma unroll
        for (int c = tid; c < 1024; c += 256) {  // 128 rows x 8 chunks per tile
            const int row = c >> 3;
            const int cb  = (c & 7) << 4;
            const uint32_t so = (uint32_t)(row * 128 + cb);
            const uint32_t sw = so ^ ((so >> 3) & 0x70);
            const size_t go = (size_t)row * rs + kb + cb;
            cp16(st + TC_OFF_AH + sw, srcAh + go);
            cp16(st + TC_OFF_AL + sw, srcAl + go);
            cp16(st + TC_OFF_BH + sw, srcBh + go);
            cp16(st + TC_OFF_BL + sw, srcBl + go);
        }
        asm volatile("cp.async.commit_group;" ::: "memory");
    };

    const int NS = KDIM / 64;   // 128 k-tiles
    fill(0, 0);
    fill(1, 1);

    for (int s = 0; s < NS; s++) {
        // local fill(s) complete (one newer group may remain in flight)
        if (s + 1 < NS) { asm volatile("cp.async.wait_group 1;" ::: "memory"); }
        else            { asm volatile("cp.async.wait_group 0;" ::: "memory"); }
        __syncthreads();

        // split cluster barrier: signal stage-s data ready; overlap refill
        // with peer skew; wait before the leader reads peer SMEM.
        CLUSTER_ARRIVE();

        // refill stage (s+2)%3 == (s-1)%3: gated on MMA(s-1) completion
        // (multicast commit lands in BOTH CTAs' local mma mbar).
        if (s + 2 < NS) {
            if (s >= 1) {
                MBARRIER_WAIT_PARITY(sb + TC_HDR + 8 + ((s - 1) & 1) * 8,
                                     ((s - 1) >> 1) & 1);
            }
            fill((s + 2) % 3, s + 2);
        }

        CLUSTER_WAIT();   // both CTAs' stage-s tiles complete + visible

        if (rank == 0 && warp == 0 && elect_one()) {
            asm volatile("fence.proxy.async.shared::cta;" ::: "memory");
            const uint32_t st = sb + (s % 3) * TC_ST;
            const uint64_t dAh = make_desc(st + TC_OFF_AH);
            const uint64_t dAl = make_desc(st + TC_OFF_AL);
            const uint64_t dBh = make_desc(st + TC_OFF_BH);
            const uint64_t dBl = make_desc(st + TC_OFF_BL);
            #pragma unroll
            for (int c = 0; c < 4; c++) {
                mma_ss_f16_cg2(tmem, dAh + c * 2, dBh + c * 2, TC_IDESC,
                               (s | c) ? 1u : 0u);
                mma_ss_f16_cg2(tmem, dAh + c * 2, dBl + c * 2, TC_IDESC, 1u);
                mma_ss_f16_cg2(tmem, dAl + c * 2, dBh + c * 2, TC_IDESC, 1u);
            }
            TCGEN05_COMMIT_MC_CG2(sb + TC_HDR + 8 + (s & 1) * 8, 0x3);
        }
    }

    // final MMA completion (in-order queue: commit NS-1 covers all prior)
    MBARRIER_WAIT_PARITY(sb + TC_HDR + 8 + ((NS - 1) & 1) * 8,
                         ((NS - 1) >> 1) & 1);
    TCGEN05_FENCE_AFTER();

    // Epilogue: this CTA's TMEM holds its 128 M-rows x 256 cols.
    // warp w: TMEM lanes (w&3)*32, cols (w>>2)*128 .. +127; each 32-col
    // group is one full multivector -> fused normalization, no shuffles.
    const int m = bm + (int)rank * 128 + (warp & 3) * 32 + lane;
    const int colbase = (warp >> 2) * 128;
    #pragma unroll 1
    for (int g = 0; g < 4; g++) {
        uint32_t r[32];
        TCGEN05_LD_32X32B_X32(r, tmem + colbase + g * 32);
        TCGEN05_WAIT_LD();
        float a[32];
        float nsq = 0.f, l2sq = 0.f;
        #pragma unroll
        for (int k = 0; k < 32; k++) {
            a[k] = __uint_as_float(r[k]);
            const float sq = a[k] * a[k];
            l2sq += sq;
            nsq += sig_of(k) * sq;
        }
        float denom = fmaxf(sqrtf(fabsf(nsq) + 1e-6f), sqrtf(l2sq) * 0.25f + 1e-6f);
        denom = fmaxf(denom, 1.0f);
        const float inv = 1.0f / denom;
        float4* dst = (float4*)(out + (size_t)m * NDIM + bn + colbase + g * 32);
        #pragma unroll
        for (int k = 0; k < 8; k++)
            dst[k] = make_float4(a[4 * k] * inv, a[4 * k + 1] * inv,
                                 a[4 * k + 2] * inv, a[4 * k + 3] * inv);
    }

    __syncthreads();
    if (tid == 0) {
        MBARRIER_INVAL(sb + TC_HDR + 8);
        MBARRIER_INVAL(sb + TC_HDR + 16);
    }
    __syncthreads();
    if (warp == 0) {
        TCGEN05_RELINQ_CG2();
        TCGEN05_DEALLOC_CG2(tmem, 256);
    }
    CLUSTER_SYNC();   // no CTA exits while peer ops may target its smem
#else
    (void)out;   // HMMA fallback does the work in this cubin
#endif
}

// ================= HMMA fallback (non-'a' cubin only) =======================
static constexpr int ROWB   = 80;
static constexpr int TILE_B = 128 * ROWB;
static constexpr int STG_B  = 4 * TILE_B;
static constexpr int MM_SMEM = 2 * STG_B;

__global__ void __launch_bounds__(256, 2) versor_mma(float* __restrict__ out) {
#if !HAS_TCGEN05
    extern __shared__ __align__(128) char smem[];
    const uint32_t sb = smem_u32(smem);
    const int tid  = threadIdx.x;
    const int lane = tid & 31;
    const int warp = tid >> 5;
    const int wm = warp >> 2;
    const int wn = warp & 3;

    const int pid = blockIdx.x;
    const int grp = pid >> 9;
    const int rem = pid & 511;
    const int pm  = (grp << 3) + (rem & 7);
    const int pn  = rem >> 3;
    const int bm  = pm * 128;
    const int bn  = pn * 128;

    const char* src0 = (const char*)(g_Xh + (size_t)bm * KDIM);
    const char* src1 = (const char*)(g_Xl + (size_t)bm * KDIM);
    const char* src2 = (const char*)(g_Wh + (size_t)bn * KDIM);
    const char* src3 = (const char*)(g_Wl + (size_t)bn * KDIM);

    const int r0 = tid >> 2;
    const int r1 = 64 + (tid >> 2);
    const int c0 = (tid & 3) << 4;

    float acc[4][4][4];
    #pragma unroll
    for (int a = 0; a < 4; a++)
        #pragma unroll
        for (int b = 0; b < 4; b++)
            #pragma unroll
            for (int c = 0; c < 4; c++) acc[a][b][c] = 0.f;

    auto fill = [&](int buf, int kbyte) {
        const uint32_t s = sb + buf * STG_B;
        const size_t o0 = (size_t)r0 * (KDIM * 2) + kbyte + c0;
        const size_t o1 = (size_t)r1 * (KDIM * 2) + kbyte + c0;
        const uint32_t d0 = r0 * ROWB + c0;
        const uint32_t d1 = r1 * ROWB + c0;
        cp16(s + 0 * TILE_B + d0, src0 + o0);
        cp16(s + 0 * TILE_B + d1, src0 + o1);
        cp16(s + 1 * TILE_B + d0, src1 + o0);
        cp16(s + 1 * TILE_B + d1, src1 + o1);
        cp16(s + 2 * TILE_B + d0, src2 + o0);
        cp16(s + 2 * TILE_B + d1, src2 + o1);
        cp16(s + 3 * TILE_B + d0, src3 + o0);
        cp16(s + 3 * TILE_B + d1, src3 + o1);
        asm volatile("cp.async.commit_group;" ::: "memory");
    };

    fill(0, 0);

    const int NS = KDIM / 32;
    for (int s = 0; s < NS; s++) {
        if (s + 1 < NS) {
            fill((s + 1) & 1, (s + 1) * 64);
            asm volatile("cp.async.wait_group 1;" ::: "memory");
        } else {
            asm volatile("cp.async.wait_group 0;" ::: "memory");
        }
        __syncthreads();

        const uint32_t stg = sb + (s & 1) * STG_B;
        const uint32_t ahB = stg;
        const uint32_t alB = stg + TILE_B;
        const uint32_t bhB = stg + 2 * TILE_B;
        const uint32_t blB = stg + 3 * TILE_B;

        #pragma unroll
        for (int kk = 0; kk < 2; kk++) {
            const int kb = kk * 32;
            uint32_t bh[4][2], bl[4][2];
            #pragma unroll
            for (int ni = 0; ni < 4; ni++) {
                const uint32_t ra = (uint32_t)((wn * 32 + ni * 8 + (lane & 7)) * ROWB
                                               + kb + ((lane >> 3) & 1) * 16);
                ldsm_x2(bh[ni], bhB + ra);
                ldsm_x2(bl[ni], blB + ra);
            }
            #pragma unroll
            for (int mi = 0; mi < 4; mi++) {
                const uint32_t raA = (uint32_t)((wm * 64 + mi * 16 + (lane & 15)) * ROWB
                                                + kb + ((lane >> 4) & 1) * 16);
                uint32_t ah[4], al[4];
                ldsm_x4(ah, ahB + raA);
                ldsm_x4(al, alB + raA);
                #pragma unroll
                for (int ni = 0; ni < 4; ni++) {
                    mma16816(acc[mi][ni], ah, bh[ni]);
                    mma16816(acc[mi][ni], ah, bl[ni]);
                    mma16816(acc[mi][ni], al, bh[ni]);
                }
            }
        }
        __syncthreads();
    }

    float sg[4][2];
    #pragma unroll
    for (int ni = 0; ni < 4; ni++) {
        const int k0 = ni * 8 + (lane & 3) * 2;
        sg[ni][0] = sig_of(k0);
        sg[ni][1] = sig_of(k0 + 1);
    }

    #pragma unroll
    for (int mi = 0; mi < 4; mi++) {
        #pragma unroll
        for (int h = 0; h < 2; h++) {
            float nsq = 0.f, l2sq = 0.f;
            #pragma unroll
            for (int ni = 0; ni < 4; ni++) {
                const float v0 = acc[mi][ni][2 * h + 0];
                const float v1 = acc[mi][ni][2 * h + 1];
                const float q0 = v0 * v0, q1 = v1 * v1;
                l2sq += q0 + q1;
                nsq  += sg[ni][0] * q0 + sg[ni][1] * q1;
            }
            nsq  += __shfl_xor_sync(0xFFFFFFFFu, nsq, 1);
            l2sq += __shfl_xor_sync(0xFFFFFFFFu, l2sq, 1);
            nsq  += __shfl_xor_sync(0xFFFFFFFFu, nsq, 2);
            l2sq += __shfl_xor_sync(0xFFFFFFFFu, l2sq, 2);

            float denom = fmaxf(sqrtf(fabsf(nsq) + 1e-6f),
                                sqrtf(l2sq) * 0.25f + 1e-6f);
            denom = fmaxf(denom, 1.0f);
            const float inv = 1.0f / denom;

            const int row = bm + wm * 64 + mi * 16 + h * 8 + (lane >> 2);
            float* orow = out + (size_t)row * NDIM + bn + wn * 32 + (lane & 3) * 2;
            #pragma unroll
            for (int ni = 0; ni < 4; ni++) {
                *(float2*)(orow + ni * 8) =
                    make_float2(acc[mi][ni][2 * h + 0] * inv,
                                acc[mi][ni][2 * h + 1] * inv);
            }
        }
    }
#else
    (void)out;   // tcgen05 kernel does the work in this cubin
#endif
}

// ============================== launch ======================================
extern "C" void kernel_launch(void* const* d_in, const int* in_sizes, int n_in,
                              void* d_out, int out_size) {
    (void)in_sizes; (void)n_in; (void)out_size;
    const float* x = (const float*)d_in[0];
    const float* w = (const float*)d_in[1];
    float* out = (float*)d_out;

    init_sign_k<<<1, dim3(32, 32)>>>();
    cvt_x_k<<<(int)(((size_t)MDIM * KDIM) / 1024), 256>>>(x);
    build_w_k<<<(int)(((size_t)NDIM * KDIM) / 1024), 256>>>(w);

    cudaFuncSetAttribute(versor_tc,
                         cudaFuncAttributeMaxDynamicSharedMemorySize, TC_SMEM);
    versor_tc<<<2048, 256, TC_SMEM>>>(out);

    cudaFuncSetAttribute(versor_mma,
                         cudaFuncAttributeMaxDynamicSharedMemorySize, MM_SMEM);
    versor_mma<<<64 * 64, 256, MM_SMEM>>>(out);
}

// round 13
// speedup vs baseline: 1.0872x; 1.0872x over previous
#include <cuda_runtime.h>
#include <cuda_bf16.h>
#include <cstdint>

// ============================================================================
// VersorLinear == one 8192x8192x8192 GEMM with a signed/permuted weight:
//   out[bs, o*32+k] = sum_{i,l} x[bs, i*32+l] * sign(k^l, l) * weight[o,i,k^l]
// followed by per-(bs,o) manifold normalization over the 32 components.
//
// R12: cg2 GEMM, software-pipelined MMA issue. R11 proved correctness but
// exposed the mma(s-1) completion wait on the critical path (tensor 48.6%).
// Reorder: issue MMA(s) right after the cluster barrier, THEN wait mma(s-1)
// and refill -> tensor pipe always has the next tile queued.
// M=256 x N=256 pair tiles, BK=64, 3-stage cp.async, multicast commit,
// 3-term bf16 split, fp32 TMEM acc, fused normalization.
// ============================================================================

#if defined(__CUDA_ARCH_FEAT_SM103_ALL) || defined(__CUDA_ARCH_FEAT_SM100_ALL) || \
    defined(__CUDA_ARCH_FEAT_SM101_ALL) ||                                        \
    (defined(__CUDA_ARCH_SPECIFIC__) && (__CUDA_ARCH_SPECIFIC__ == 1030 || __CUDA_ARCH_SPECIFIC__ == 1000))
#define HAS_TCGEN05 1
#else
#define HAS_TCGEN05 0
#endif

static constexpr int MDIM = 8192;   // B*S
static constexpr int NDIM = 8192;   // OUT_F*32
static constexpr int KDIM = 8192;   // IN_F*32
static constexpr int IFEA = 256;

// ---- static device scratch (1024-aligned for 16B vector access) ----
__device__ __align__(1024) float g_sign[1024];
__device__ __align__(1024) __nv_bfloat16 g_Xh[(size_t)MDIM * KDIM];
__device__ __align__(1024) __nv_bfloat16 g_Xl[(size_t)MDIM * KDIM];
__device__ __align__(1024) __nv_bfloat16 g_Wh[(size_t)NDIM * KDIM];
__device__ __align__(1024) __nv_bfloat16 g_Wl[(size_t)NDIM * KDIM];

// ============================ common helpers ================================
__device__ __forceinline__ uint32_t smem_u32(const void* p) {
    uint32_t a;
    asm("{ .reg .u64 t; cvta.to.shared.u64 t, %1; cvt.u32.u64 %0, t; }"
        : "=r"(a) : "l"(p));
    return a;
}

__device__ __forceinline__ void cp16(uint32_t sdst, const void* gsrc) {
    asm volatile("cp.async.cg.shared.global [%0], [%1], 16;"
                 :: "r"(sdst), "l"(gsrc));
}

__device__ __forceinline__ bool elect_one() {
    uint32_t p;
    asm volatile(
        "{\n\t.reg .pred p;\n\t"
        "elect.sync _|p, 0xFFFFFFFF;\n\t"
        "selp.b32 %0, 1, 0, p;\n\t}"
        : "=r"(p));
    return p != 0;
}

// metric signature factor for blade k
__device__ __forceinline__ float sig_of(int k) {
    const int g = __popc(k);
    const int neg = ((k >> 4) & 1) ^ ((g * (g - 1) / 2) & 1);
    return neg ? -1.f : 1.f;
}

// ============================ tcgen05 helpers ===============================
#if HAS_TCGEN05

__device__ __forceinline__ uint32_t cluster_rank() {
    uint32_t r;
    asm("mov.u32 %0, %%cluster_ctarank;" : "=r"(r));
    return r;
}

#define TCGEN05_ALLOC_CG2(smem_addr, ncols) \
    asm volatile("tcgen05.alloc.cta_group::2.sync.aligned.shared::cta.b32 [%0], %1;" \
                 :: "r"((uint32_t)(smem_addr)), "r"((uint32_t)(ncols)) : "memory")
#define TCGEN05_RELINQ_CG2() \
    asm volatile("tcgen05.relinquish_alloc_permit.cta_group::2.sync.aligned;")
#define TCGEN05_DEALLOC_CG2(tmem, ncols) \
    asm volatile("tcgen05.dealloc.cta_group::2.sync.aligned.b32 %0, %1;" \
                 :: "r"(tmem), "r"((uint32_t)(ncols)))
#define TCGEN05_COMMIT_MC_CG2(mbar, mask) \
    asm volatile("tcgen05.commit.cta_group::2.mbarrier::arrive::one.shared::cluster.multicast::cluster.b64 [%0], %1;" \
                 :: "r"((uint32_t)(mbar)), "h"((uint16_t)(mask)) : "memory")
#define TCGEN05_WAIT_LD() asm volatile("tcgen05.wait::ld.sync.aligned;" ::: "memory")
#define TCGEN05_FENCE_AFTER() asm volatile("tcgen05.fence::after_thread_sync;" ::: "memory")
#define MBARRIER_INIT(mbar, count) \
    asm volatile("mbarrier.init.shared.b64 [%0], %1;" \
                 :: "r"((uint32_t)(mbar)), "r"((uint32_t)(count)) : "memory")
#define MBARRIER_INVAL(mbar) \
    asm volatile("mbarrier.inval.shared.b64 [%0];" :: "r"((uint32_t)(mbar)) : "memory")

#define MBARRIER_WAIT_PARITY(mbar_addr, phase_parity) do {                          \
    uint32_t _mbar = (uint32_t)(mbar_addr);                                         \
    uint32_t _parity = (uint32_t)(phase_parity);                                    \
    uint32_t _done;                                                                 \
    asm volatile(                                                                   \
        "{\n\t.reg .pred p;\n\t"                                                    \
        "mbarrier.try_wait.parity.acquire.cta.shared::cta.b64 p, [%1], %2;\n\t"     \
        "selp.b32 %0, 1, 0, p;\n\t}"                                                \
        : "=r"(_done) : "r"(_mbar), "r"(_parity) : "memory");                       \
    if (!_done) {                                                                   \
        asm volatile(                                                               \
            "{\n\t.reg .pred P1;\n\t"                                               \
            "WAIT_LOOP_%=:\n\t"                                                     \
            "mbarrier.try_wait.parity.acquire.cta.shared::cta.b64 P1, [%0], %1, 0x989680;\n\t" \
            "@P1 bra.uni WAIT_DONE_%=;\n\t"                                         \
            "bra.uni WAIT_LOOP_%=;\n\t"                                             \
            "WAIT_DONE_%=:\n\t}"                                                    \
            :: "r"(_mbar), "r"(_parity) : "memory");                                \
    }                                                                               \
} while (0)

#define TCGEN05_LD_32X32B_X32(r, tmem_addr) \
    asm volatile( \
        "tcgen05.ld.sync.aligned.32x32b.x32.b32 " \
        "{%0, %1, %2, %3, %4, %5, %6, %7, " \
        " %8, %9, %10, %11, %12, %13, %14, %15, " \
        " %16, %17, %18, %19, %20, %21, %22, %23, " \
        " %24, %25, %26, %27, %28, %29, %30, %31}, [%32];" \
        : "=r"((r)[0]),  "=r"((r)[1]),  "=r"((r)[2]),  "=r"((r)[3]), \
          "=r"((r)[4]),  "=r"((r)[5]),  "=r"((r)[6]),  "=r"((r)[7]), \
          "=r"((r)[8]),  "=r"((r)[9]),  "=r"((r)[10]), "=r"((r)[11]), \
          "=r"((r)[12]), "=r"((r)[13]), "=r"((r)[14]), "=r"((r)[15]), \
          "=r"((r)[16]), "=r"((r)[17]), "=r"((r)[18]), "=r"((r)[19]), \
          "=r"((r)[20]), "=r"((r)[21]), "=r"((r)[22]), "=r"((r)[23]), \
          "=r"((r)[24]), "=r"((r)[25]), "=r"((r)[26]), "=r"((r)[27]), \
          "=r"((r)[28]), "=r"((r)[29]), "=r"((r)[30]), "=r"((r)[31]) \
        : "r"(tmem_addr))

static constexpr uint64_t DESC_BASE_SW128 =
    (uint64_t(2) << 61) | (uint64_t(1) << 46) | (uint64_t(64) << 32) | (uint64_t(1) << 16);

__device__ __forceinline__ uint64_t make_desc(uint32_t addr) {
    return DESC_BASE_SW128 | ((uint64_t)(addr >> 4) & 0x3FFF);
}

// cg2 bf16 SS MMA: disable-output-lane vector is 8 regs for cta_group::2
__device__ __forceinline__ void mma_ss_f16_cg2(uint32_t d, uint64_t a, uint64_t b,
                                               uint32_t idesc, uint32_t en) {
    asm volatile(
        "{\n\t.reg .pred p;\n\t"
        "setp.ne.u32 p, %4, 0;\n\t"
        "tcgen05.mma.cta_group::2.kind::f16 [%0], %1, %2, %3, "
        "{%5, %5, %5, %5, %5, %5, %5, %5}, p;\n\t}"
        :: "r"(d), "l"(a), "l"(b), "r"(idesc), "r"(en), "r"(0u)
        : "memory");
}

#define CLUSTER_ARRIVE() \
    asm volatile("barrier.cluster.arrive.aligned;" ::: "memory")
#define CLUSTER_WAIT() \
    asm volatile("barrier.cluster.wait.aligned;" ::: "memory")
#define CLUSTER_SYNC() do { CLUSTER_ARRIVE(); CLUSTER_WAIT(); } while (0)

#endif // HAS_TCGEN05

// ============================ HMMA helpers (fallback) =======================
#if !HAS_TCGEN05
__device__ __forceinline__ void ldsm_x4(uint32_t* r, uint32_t addr) {
    asm volatile("ldmatrix.sync.aligned.m8n8.x4.shared.b16 {%0,%1,%2,%3}, [%4];"
                 : "=r"(r[0]), "=r"(r[1]), "=r"(r[2]), "=r"(r[3]) : "r"(addr));
}
__device__ __forceinline__ void ldsm_x2(uint32_t* r, uint32_t addr) {
    asm volatile("ldmatrix.sync.aligned.m8n8.x2.shared.b16 {%0,%1}, [%2];"
                 : "=r"(r[0]), "=r"(r[1]) : "r"(addr));
}
__device__ __forceinline__ void mma16816(float* c, const uint32_t* a, const uint32_t* b) {
    asm volatile(
        "mma.sync.aligned.m16n8k16.row.col.f32.bf16.bf16.f32 "
        "{%0,%1,%2,%3}, {%4,%5,%6,%7}, {%8,%9}, {%0,%1,%2,%3};"
        : "+f"(c[0]), "+f"(c[1]), "+f"(c[2]), "+f"(c[3])
        : "r"(a[0]), "r"(a[1]), "r"(a[2]), "r"(a[3]), "r"(b[0]), "r"(b[1]));
}
#endif

// ============================ builder kernels ===============================
__global__ void init_sign_k() {
    int a = threadIdx.x, b = threadIdx.y;
    float s = 1.f;
    int bits = a;
    for (int i = 0; i < 5; i++) {
        if ((b >> i) & 1) {
            for (int j = i + 1; j < 5; j++)
                if ((bits >> j) & 1) s = -s;
            if ((bits >> i) & 1) {
                if (i == 4) s = -s;   // e5^2 = -1
                bits &= ~(1 << i);
            } else {
                bits |= (1 << i);
            }
        }
    }
    g_sign[a * 32 + b] = s;
}

__global__ void __launch_bounds__(256) cvt_x_k(const float* __restrict__ x) {
    const size_t i = ((size_t)blockIdx.x * blockDim.x + threadIdx.x) * 4;
    const float4 v = *(const float4*)(x + i);
    __nv_bfloat16 h0 = __float2bfloat16(v.x);
    __nv_bfloat16 h1 = __float2bfloat16(v.y);
    __nv_bfloat16 h2 = __float2bfloat16(v.z);
    __nv_bfloat16 h3 = __float2bfloat16(v.w);
    __nv_bfloat16 l0 = __float2bfloat16(v.x - __bfloat162float(h0));
    __nv_bfloat16 l1 = __float2bfloat16(v.y - __bfloat162float(h1));
    __nv_bfloat16 l2 = __float2bfloat16(v.z - __bfloat162float(h2));
    __nv_bfloat16 l3 = __float2bfloat16(v.w - __bfloat162float(h3));
    __nv_bfloat162 H01 = __halves2bfloat162(h0, h1);
    __nv_bfloat162 H23 = __halves2bfloat162(h2, h3);
    __nv_bfloat162 L01 = __halves2bfloat162(l0, l1);
    __nv_bfloat162 L23 = __halves2bfloat162(l2, l3);
    uint2 uh, ul;
    uh.x = *(uint32_t*)&H01; uh.y = *(uint32_t*)&H23;
    ul.x = *(uint32_t*)&L01; ul.y = *(uint32_t*)&L23;
    *(uint2*)(g_Xh + i) = uh;
    *(uint2*)(g_Xl + i) = ul;
}

__global__ void __launch_bounds__(256) build_w_k(const float* __restrict__ w) {
    const size_t idx = ((size_t)blockIdx.x * blockDim.x + threadIdx.x) * 4;
    const int q = (int)(idx & 8191);     // (i,l)
    const int n = (int)(idx >> 13);      // (o,k)
    const int l0 = q & 31, i = q >> 5;
    const int k = n & 31, o = n >> 5;
    const float* wrow = w + ((size_t)(o * IFEA + i) << 5);

    __nv_bfloat16 h[4], lo[4];
    #pragma unroll
    for (int d = 0; d < 4; d++) {
        const int l = l0 + d;
        const int j = k ^ l;
        const float v = g_sign[j * 32 + l] * wrow[j];
        h[d] = __float2bfloat16(v);
        lo[d] = __float2bfloat16(v - __bfloat162float(h[d]));
    }
    __nv_bfloat162 H01 = __halves2bfloat162(h[0], h[1]);
    __nv_bfloat162 H23 = __halves2bfloat162(h[2], h[3]);
    __nv_bfloat162 L01 = __halves2bfloat162(lo[0], lo[1]);
    __nv_bfloat162 L23 = __halves2bfloat162(lo[2], lo[3]);
    uint2 uh, ul;
    uh.x = *(uint32_t*)&H01; uh.y = *(uint32_t*)&H23;
    ul.x = *(uint32_t*)&L01; ul.y = *(uint32_t*)&L23;
    *(uint2*)(g_Wh + idx) = uh;
    *(uint2*)(g_Wl + idx) = ul;
}

// ====================== tcgen05 cg2 GEMM (main) =============================
// Pair tile: M=256, N=256, BK=64. Per CTA per stage: Ah/Al (16KB each, its
// 128 M-rows) + Bh/Bl (16KB each, its 128 N-rows = N/2 split). 64KB * 3 stages.
static constexpr int TC_ST      = 65536;
static constexpr int TC_OFF_AH  = 0;
static constexpr int TC_OFF_AL  = 16384;
static constexpr int TC_OFF_BH  = 32768;
static constexpr int TC_OFF_BL  = 49152;
static constexpr int TC_HDR     = 3 * TC_ST;        // 196608
static constexpr int TC_SMEM    = TC_HDR + 32;
// header: +0 tmem ptr, +8 mma[0], +16 mma[1] (multicast commit targets)

// idesc: dtype=F32, a=BF16, b=BF16, N=256, M=256
static constexpr uint32_t TC_IDESC =
    (1u << 4) | (1u << 7) | (1u << 10) | ((256u / 8) << 17) | ((256u / 16) << 24);

__global__ void __launch_bounds__(256) __cluster_dims__(2, 1, 1)
versor_tc(float* __restrict__ out) {
#if HAS_TCGEN05
    extern __shared__ __align__(1024) char smem[];
    const uint32_t sb = smem_u32(smem);
    const int tid  = threadIdx.x;
    const int warp = tid >> 5;
    const int lane = tid & 31;
    const uint32_t rank = cluster_rank();

    // cg2 TMEM alloc: warp 0 of BOTH CTAs participates. No relinquish race.
    if (warp == 0) { TCGEN05_ALLOC_CG2(sb + TC_HDR, 256); }
    if (tid == 0) {
        MBARRIER_INIT(sb + TC_HDR + 8, 1);   // mma[0]
        MBARRIER_INIT(sb + TC_HDR + 16, 1);  // mma[1]
    }
    __syncthreads();
    CLUSTER_SYNC();   // mbars initialized before any multicast commit arrives

    uint32_t tmem;
    asm volatile("ld.shared.b32 %0, [%1];" : "=r"(tmem) : "r"(sb + TC_HDR));

    // pair-tile grid: 32 (M) x 32 (N); grouped raster GM=8 over pairs
    const int pair = blockIdx.x >> 1;
    const int grp  = pair >> 8;          // / (8*32)
    const int rem  = pair & 255;
    const int pm   = (grp << 3) + (rem & 7);
    const int pn   = rem >> 3;
    const int bm   = pm * 256;
    const int bn   = pn * 256;

    // this CTA's slices: A rows [bm + rank*128, +128), B rows [bn + rank*128, +128)
    const char* srcAh = (const char*)(g_Xh + (size_t)(bm + rank * 128) * KDIM);
    const char* srcAl = (const char*)(g_Xl + (size_t)(bm + rank * 128) * KDIM);
    const char* srcBh = (const char*)(g_Wh + (size_t)(bn + rank * 128) * KDIM);
    const char* srcBl = (const char*)(g_Wl + (size_t)(bn + rank * 128) * KDIM);
    const size_t rs = (size_t)KDIM * 2;

    auto fill = [&](int stage, int ktile) {
        const uint32_t st = sb + stage * TC_ST;
        const size_t kb = (size_t)ktile * 128;   // 64 k * 2B
        #pragma unroll
        for (int c = tid; c < 1024; c += 256) {  // 128 rows x 8 chunks per tile
            const int row = c >> 3;
            const int cb  = (c & 7) << 4;
            const uint32_t so = (uint32_t)(row * 128 + cb);
            const uint32_t sw = so ^ ((so >> 3) & 0x70);
            const size_t go = (size_t)row * rs + kb + cb;
            cp16(st + TC_OFF_AH + sw, srcAh + go);
            cp16(st + TC_OFF_AL + sw, srcAl + go);
            cp16(st + TC_OFF_BH + sw, srcBh + go);
            cp16(st + TC_OFF_BL + sw, srcBl + go);
        }
        asm volatile("cp.async.commit_group;" ::: "memory");
    };

    const int NS = KDIM / 64;   // 128 k-tiles
    fill(0, 0);
    fill(1, 1);

    for (int s = 0; s < NS; s++) {
        // local fill(s) complete (one newer group may remain in flight)
        if (s + 1 < NS) { asm volatile("cp.async.wait_group 1;" ::: "memory"); }
        else            { asm volatile("cp.async.wait_group 0;" ::: "memory"); }
        __syncthreads();

        // cluster barrier: both CTAs' stage-s tiles complete + visible
        CLUSTER_ARRIVE();
        CLUSTER_WAIT();

        // issue MMA(s) FIRST so the tensor pipe always has work queued
        if (rank == 0 && warp == 0 && elect_one()) {
            asm volatile("fence.proxy.async.shared::cta;" ::: "memory");
            const uint32_t st = sb + (s % 3) * TC_ST;
            const uint64_t dAh = make_desc(st + TC_OFF_AH);
            const uint64_t dAl = make_desc(st + TC_OFF_AL);
            const uint64_t dBh = make_desc(st + TC_OFF_BH);
            const uint64_t dBl = make_desc(st + TC_OFF_BL);
            #pragma unroll
            for (int c = 0; c < 4; c++) {
                mma_ss_f16_cg2(tmem, dAh + c * 2, dBh + c * 2, TC_IDESC,
                               (s | c) ? 1u : 0u);
                mma_ss_f16_cg2(tmem, dAh + c * 2, dBl + c * 2, TC_IDESC, 1u);
                mma_ss_f16_cg2(tmem, dAl + c * 2, dBh + c * 2, TC_IDESC, 1u);
            }
            TCGEN05_COMMIT_MC_CG2(sb + TC_HDR + 8 + (s & 1) * 8, 0x3);
        }

        // THEN wait MMA(s-1) done (its buffer (s+2)%3 == (s-1)%3) and refill.
        // The wait overlaps with MMA(s) already queued behind it.
        if (s + 2 < NS) {
            if (s >= 1) {
                MBARRIER_WAIT_PARITY(sb + TC_HDR + 8 + ((s - 1) & 1) * 8,
                                     ((s - 1) >> 1) & 1);
            }
            fill((s + 2) % 3, s + 2);
        }
    }

    // final MMA completion (in-order queue: commit NS-1 covers all prior)
    MBARRIER_WAIT_PARITY(sb + TC_HDR + 8 + ((NS - 1) & 1) * 8,
                         ((NS - 1) >> 1) & 1);
    TCGEN05_FENCE_AFTER();

    // Epilogue: this CTA's TMEM holds its 128 M-rows x 256 cols.
    // warp w: TMEM lanes (w&3)*32, cols (w>>2)*128 .. +127; each 32-col
    // group is one full multivector -> fused normalization, no shuffles.
    const int m = bm + (int)rank * 128 + (warp & 3) * 32 + lane;
    const int colbase = (warp >> 2) * 128;
    #pragma unroll 1
    for (int g = 0; g < 4; g++) {
        uint32_t r[32];
        TCGEN05_LD_32X32B_X32(r, tmem + colbase + g * 32);
        TCGEN05_WAIT_LD();
        float a[32];
        float nsq = 0.f, l2sq = 0.f;
        #pragma unroll
        for (int k = 0; k < 32; k++) {
            a[k] = __uint_as_float(r[k]);
            const float sq = a[k] * a[k];
            l2sq += sq;
            nsq += sig_of(k) * sq;
        }
        float denom = fmaxf(sqrtf(fabsf(nsq) + 1e-6f), sqrtf(l2sq) * 0.25f + 1e-6f);
        denom = fmaxf(denom, 1.0f);
        const float inv = 1.0f / denom;
        float4* dst = (float4*)(out + (size_t)m * NDIM + bn + colbase + g * 32);
        #pragma unroll
        for (int k = 0; k < 8; k++)
            dst[k] = make_float4(a[4 * k] * inv, a[4 * k + 1] * inv,
                                 a[4 * k + 2] * inv, a[4 * k + 3] * inv);
    }

    __syncthreads();
    if (tid == 0) {
        MBARRIER_INVAL(sb + TC_HDR + 8);
        MBARRIER_INVAL(sb + TC_HDR + 16);
    }
    __syncthreads();
    if (warp == 0) {
        TCGEN05_RELINQ_CG2();
        TCGEN05_DEALLOC_CG2(tmem, 256);
    }
    CLUSTER_SYNC();   // no CTA exits while peer ops may target its smem
#else
    (void)out;   // HMMA fallback does the work in this cubin
#endif
}

// ================= HMMA fallback (non-'a' cubin only) =======================
static constexpr int ROWB   = 80;
static constexpr int TILE_B = 128 * ROWB;
static constexpr int STG_B  = 4 * TILE_B;
static constexpr int MM_SMEM = 2 * STG_B;

__global__ void __launch_bounds__(256, 2) versor_mma(float* __restrict__ out) {
#if !HAS_TCGEN05
    extern __shared__ __align__(128) char smem[];
    const uint32_t sb = smem_u32(smem);
    const int tid  = threadIdx.x;
    const int lane = tid & 31;
    const int warp = tid >> 5;
    const int wm = warp >> 2;
    const int wn = warp & 3;

    const int pid = blockIdx.x;
    const int grp = pid >> 9;
    const int rem = pid & 511;
    const int pm  = (grp << 3) + (rem & 7);
    const int pn  = rem >> 3;
    const int bm  = pm * 128;
    const int bn  = pn * 128;

    const char* src0 = (const char*)(g_Xh + (size_t)bm * KDIM);
    const char* src1 = (const char*)(g_Xl + (size_t)bm * KDIM);
    const char* src2 = (const char*)(g_Wh + (size_t)bn * KDIM);
    const char* src3 = (const char*)(g_Wl + (size_t)bn * KDIM);

    const int r0 = tid >> 2;
    const int r1 = 64 + (tid >> 2);
    const int c0 = (tid & 3) << 4;

    float acc[4][4][4];
    #pragma unroll
    for (int a = 0; a < 4; a++)
        #pragma unroll
        for (int b = 0; b < 4; b++)
            #pragma unroll
            for (int c = 0; c < 4; c++) acc[a][b][c] = 0.f;

    auto fill = [&](int buf, int kbyte) {
        const uint32_t s = sb + buf * STG_B;
        const size_t o0 = (size_t)r0 * (KDIM * 2) + kbyte + c0;
        const size_t o1 = (size_t)r1 * (KDIM * 2) + kbyte + c0;
        const uint32_t d0 = r0 * ROWB + c0;
        const uint32_t d1 = r1 * ROWB + c0;
        cp16(s + 0 * TILE_B + d0, src0 + o0);
        cp16(s + 0 * TILE_B + d1, src0 + o1);
        cp16(s + 1 * TILE_B + d0, src1 + o0);
        cp16(s + 1 * TILE_B + d1, src1 + o1);
        cp16(s + 2 * TILE_B + d0, src2 + o0);
        cp16(s + 2 * TILE_B + d1, src2 + o1);
        cp16(s + 3 * TILE_B + d0, src3 + o0);
        cp16(s + 3 * TILE_B + d1, src3 + o1);
        asm volatile("cp.async.commit_group;" ::: "memory");
    };

    fill(0, 0);

    const int NS = KDIM / 32;
    for (int s = 0; s < NS; s++) {
        if (s + 1 < NS) {
            fill((s + 1) & 1, (s + 1) * 64);
            asm volatile("cp.async.wait_group 1;" ::: "memory");
        } else {
            asm volatile("cp.async.wait_group 0;" ::: "memory");
        }
        __syncthreads();

        const uint32_t stg = sb + (s & 1) * STG_B;
        const uint32_t ahB = stg;
        const uint32_t alB = stg + TILE_B;
        const uint32_t bhB = stg + 2 * TILE_B;
        const uint32_t blB = stg + 3 * TILE_B;

        #pragma unroll
        for (int kk = 0; kk < 2; kk++) {
            const int kb = kk * 32;
            uint32_t bh[4][2], bl[4][2];
            #pragma unroll
            for (int ni = 0; ni < 4; ni++) {
                const uint32_t ra = (uint32_t)((wn * 32 + ni * 8 + (lane & 7)) * ROWB
                                               + kb + ((lane >> 3) & 1) * 16);
                ldsm_x2(bh[ni], bhB + ra);
                ldsm_x2(bl[ni], blB + ra);
            }
            #pragma unroll
            for (int mi = 0; mi < 4; mi++) {
                const uint32_t raA = (uint32_t)((wm * 64 + mi * 16 + (lane & 15)) * ROWB
                                                + kb + ((lane >> 4) & 1) * 16);
                uint32_t ah[4], al[4];
                ldsm_x4(ah, ahB + raA);
                ldsm_x4(al, alB + raA);
                #pragma unroll
                for (int ni = 0; ni < 4; ni++) {
                    mma16816(acc[mi][ni], ah, bh[ni]);
                    mma16816(acc[mi][ni], ah, bl[ni]);
                    mma16816(acc[mi][ni], al, bh[ni]);
                }
            }
        }
        __syncthreads();
    }

    float sg[4][2];
    #pragma unroll
    for (int ni = 0; ni < 4; ni++) {
        const int k0 = ni * 8 + (lane & 3) * 2;
        sg[ni][0] = sig_of(k0);
        sg[ni][1] = sig_of(k0 + 1);
    }

    #pragma unroll
    for (int mi = 0; mi < 4; mi++) {
        #pragma unroll
        for (int h = 0; h < 2; h++) {
            float nsq = 0.f, l2sq = 0.f;
            #pragma unroll
            for (int ni = 0; ni < 4; ni++) {
                const float v0 = acc[mi][ni][2 * h + 0];
                const float v1 = acc[mi][ni][2 * h + 1];
                const float q0 = v0 * v0, q1 = v1 * v1;
                l2sq += q0 + q1;
                nsq  += sg[ni][0] * q0 + sg[ni][1] * q1;
            }
            nsq  += __shfl_xor_sync(0xFFFFFFFFu, nsq, 1);
            l2sq += __shfl_xor_sync(0xFFFFFFFFu, l2sq, 1);
            nsq  += __shfl_xor_sync(0xFFFFFFFFu, nsq, 2);
            l2sq += __shfl_xor_sync(0xFFFFFFFFu, l2sq, 2);

            float denom = fmaxf(sqrtf(fabsf(nsq) + 1e-6f),
                                sqrtf(l2sq) * 0.25f + 1e-6f);
            denom = fmaxf(denom, 1.0f);
            const float inv = 1.0f / denom;

            const int row = bm + wm * 64 + mi * 16 + h * 8 + (lane >> 2);
            float* orow = out + (size_t)row * NDIM + bn + wn * 32 + (lane & 3) * 2;
            #pragma unroll
            for (int ni = 0; ni < 4; ni++) {
                *(float2*)(orow + ni * 8) =
                    make_float2(acc[mi][ni][2 * h + 0] * inv,
                                acc[mi][ni][2 * h + 1] * inv);
            }
        }
    }
#else
    (void)out;   // tcgen05 kernel does the work in this cubin
#endif
}

// ============================== launch ======================================
extern "C" void kernel_launch(void* const* d_in, const int* in_sizes, int n_in,
                              void* d_out, int out_size) {
    (void)in_sizes; (void)n_in; (void)out_size;
    const float* x = (const float*)d_in[0];
    const float* w = (const float*)d_in[1];
    float* out = (float*)d_out;

    init_sign_k<<<1, dim3(32, 32)>>>();
    cvt_x_k<<<(int)(((size_t)MDIM * KDIM) / 1024), 256>>>(x);
    build_w_k<<<(int)(((size_t)NDIM * KDIM) / 1024), 256>>>(w);

    cudaFuncSetAttribute(versor_tc,
                         cudaFuncAttributeMaxDynamicSharedMemorySize, TC_SMEM);
    versor_tc<<<2048, 256, TC_SMEM>>>(out);

    cudaFuncSetAttribute(versor_mma,
                         cudaFuncAttributeMaxDynamicSharedMemorySize, MM_SMEM);
    versor_mma<<<64 * 64, 256, MM_SMEM>>>(out);
}